// round 1
// baseline (speedup 1.0000x reference)
#include <cuda_runtime.h>
#include <math.h>

namespace {
constexpr int B = 16, T = 100, N = 128, D = 3;
constexpr int FRAMES = B * T;                 // 1600
constexpr float MIN_DIST = 0.05f;
constexpr float R2 = MIN_DIST * MIN_DIST;     // 0.0025
}

// Deterministic per-frame partials (no device malloc allowed -> __device__ globals)
__device__ float g_pen[FRAMES];
__device__ float g_work[FRAMES];
__device__ float g_stab[FRAMES];
__device__ float g_ke0[FRAMES];
__device__ float g_ke1[FRAMES];

__global__ __launch_bounds__(128) void frame_kernel(
    const float* __restrict__ traj,
    const float* __restrict__ vel,
    const float* __restrict__ frc)
{
    const int f = blockIdx.x;      // frame index = b*T + t
    const int t = f % T;
    const int i = threadIdx.x;     // point index 0..127

    __shared__ float4 spos[N];     // padded to float4 -> 1 LDS.128 per pair

    const float* pt = traj + (size_t)f * (N * D);

    // Cooperative coalesced load of 384 floats, scattered into float4 slots.
    float* sraw = reinterpret_cast<float*>(spos);
    #pragma unroll
    for (int q = i; q < N * D; q += 128) {
        int p = q / 3;
        int e = q - 3 * p;
        sraw[4 * p + e] = pt[q];
    }
    __syncthreads();

    const float4 me = spos[i];

    // ---- penetration: full off-diagonal sum, halved (symmetry == triu sum) ----
    float pen = 0.f;
    #pragma unroll 8
    for (int k = 0; k < N; ++k) {
        float4 qq = spos[k];       // broadcast (all lanes same address): conflict-free
        float dx = me.x - qq.x;
        float dy = me.y - qq.y;
        float dz = me.z - qq.z;
        float d2 = dx * dx + dy * dy + dz * dz;
        if (d2 < R2 && k != i) {   // extremely rare branch -> sqrt off hot path
            pen += MIN_DIST - sqrtf(d2);
        }
    }
    pen *= 0.5f;

    // ---- energy work term: forces[b,t,i] . (pos[b,t+1,i] - pos[b,t,i]) ----
    float wrk = 0.f;
    if (t < T - 1) {
        const float* pn = pt + N * D;                 // next frame, same batch
        const float* pf = frc + (size_t)f * (N * D);
        float nx = pn[3 * i], ny = pn[3 * i + 1], nz = pn[3 * i + 2];
        float fx = pf[3 * i], fy = pf[3 * i + 1], fz = pf[3 * i + 2];
        wrk = fx * (nx - me.x) + fy * (ny - me.y) + fz * (nz - me.z);
    }

    // ---- stability (last 5 frames) and kinetic (first / last frame) ----
    float stab = 0.f, ke = 0.f;
    if (t == 0 || t >= T - 5) {
        const float* pv = vel + (size_t)f * (N * D);
        float vx = pv[3 * i], vy = pv[3 * i + 1], vz = pv[3 * i + 2];
        float v2 = vx * vx + vy * vy + vz * vz;
        if (t >= T - 5)            stab = sqrtf(v2);
        if (t == 0 || t == T - 1)  ke   = 0.5f * v2;
    }

    // ---- block reduction of (pen, wrk, stab, ke) ----
    float4 acc = make_float4(pen, wrk, stab, ke);
    #pragma unroll
    for (int off = 16; off > 0; off >>= 1) {
        acc.x += __shfl_down_sync(0xffffffffu, acc.x, off);
        acc.y += __shfl_down_sync(0xffffffffu, acc.y, off);
        acc.z += __shfl_down_sync(0xffffffffu, acc.z, off);
        acc.w += __shfl_down_sync(0xffffffffu, acc.w, off);
    }
    __shared__ float4 wsum[4];
    if ((i & 31) == 0) wsum[i >> 5] = acc;
    __syncthreads();
    if (i == 0) {
        float4 s = wsum[0];
        #pragma unroll
        for (int w = 1; w < 4; ++w) {
            s.x += wsum[w].x; s.y += wsum[w].y;
            s.z += wsum[w].z; s.w += wsum[w].w;
        }
        g_pen[f]  = s.x;
        g_work[f] = s.y;
        g_stab[f] = s.z;
        g_ke0[f]  = (t == 0)     ? s.w : 0.f;
        g_ke1[f]  = (t == T - 1) ? s.w : 0.f;
    }
}

__global__ __launch_bounds__(256) void final_kernel(float* __restrict__ out)
{
    const int i = threadIdx.x;
    float pen = 0.f, wrk = 0.f, stab = 0.f, k0 = 0.f, k1 = 0.f;
    for (int f = i; f < FRAMES; f += 256) {
        pen  += g_pen[f];
        wrk  += g_work[f];
        stab += g_stab[f];
        k0   += g_ke0[f];
        k1   += g_ke1[f];
    }
    #pragma unroll
    for (int off = 16; off > 0; off >>= 1) {
        pen  += __shfl_down_sync(0xffffffffu, pen,  off);
        wrk  += __shfl_down_sync(0xffffffffu, wrk,  off);
        stab += __shfl_down_sync(0xffffffffu, stab, off);
        k0   += __shfl_down_sync(0xffffffffu, k0,   off);
        k1   += __shfl_down_sync(0xffffffffu, k1,   off);
    }
    __shared__ float sm[8][5];
    const int w = i >> 5;
    if ((i & 31) == 0) {
        sm[w][0] = pen; sm[w][1] = wrk; sm[w][2] = stab; sm[w][3] = k0; sm[w][4] = k1;
    }
    __syncthreads();
    if (i == 0) {
        float sp = 0.f, sw = 0.f, ss = 0.f, s0 = 0.f, s1 = 0.f;
        #pragma unroll
        for (int wv = 0; wv < 8; ++wv) {
            sp += sm[wv][0]; sw += sm[wv][1]; ss += sm[wv][2];
            s0 += sm[wv][3]; s1 += sm[wv][4];
        }
        const float pen_loss  = sp / (float)B / ((float)T * (float)N * (float)(N - 1) * 0.5f);
        const float work_mean = sw / (float)(B * (T - 1) * N);
        const float stab_mean = ss / (float)(B * 5 * N);
        const float ks        = s0 / (float)(B * N);
        const float ke        = s1 / (float)(B * N);
        out[0] = 10.0f * pen_loss + stab_mean + 0.1f * fabsf(ke - ks - work_mean);
    }
}

extern "C" void kernel_launch(void* const* d_in, const int* in_sizes, int n_in,
                              void* d_out, int out_size)
{
    const float* traj = (const float*)d_in[0];
    const float* vel  = (const float*)d_in[1];
    const float* frc  = (const float*)d_in[2];

    frame_kernel<<<FRAMES, 128>>>(traj, vel, frc);
    final_kernel<<<1, 256>>>((float*)d_out);
}

// round 2
// speedup vs baseline: 1.2350x; 1.2350x over previous
#include <cuda_runtime.h>
#include <math.h>

namespace {
constexpr int B = 16, T = 100, N = 128, D = 3;
constexpr int FRAMES = B * T;                 // 1600
constexpr float MIN_DIST = 0.05f;
constexpr float R2 = MIN_DIST * MIN_DIST;     // 0.0025
constexpr float R2_GUARD = R2 + 1e-4f;        // slack for |p|^2 expansion error
}

// Deterministic per-frame partials (no device malloc -> __device__ globals)
__device__ float g_pen[FRAMES];
__device__ float g_work[FRAMES];
__device__ float g_stab[FRAMES];
__device__ float g_ke0[FRAMES];
__device__ float g_ke1[FRAMES];
__device__ unsigned int g_count;              // zero-initialized; self-resetting

__global__ __launch_bounds__(128) void fused_kernel(
    const float* __restrict__ traj,
    const float* __restrict__ vel,
    const float* __restrict__ frc,
    float* __restrict__ out)
{
    const int f = blockIdx.x;      // frame index = b*T + t
    const int t = f % T;
    const int i = threadIdx.x;     // point index 0..127

    __shared__ float4 spos[N];     // (x, y, z, |p|^2)

    const float* pt = traj + (size_t)f * (N * D);

    // Cooperative coalesced load of 384 floats into float4 slots.
    float* sraw = reinterpret_cast<float*>(spos);
    #pragma unroll
    for (int q = i; q < N * D; q += 128) {
        int p = q / 3;
        int e = q - 3 * p;
        sraw[4 * p + e] = pt[q];
    }
    __syncthreads();
    {   // fill .w = |p|^2
        float4 v = spos[i];
        spos[i].w = v.x * v.x + v.y * v.y + v.z * v.z;
    }
    __syncthreads();

    const float4 me = spos[i];
    const float m2x = -2.0f * me.x;
    const float m2y = -2.0f * me.y;
    const float m2z = -2.0f * me.z;

    // ---- penetration: cyclic triangular enumeration (each pair exactly once)
    float pen = 0.f;
    #pragma unroll 9
    for (int j = 1; j < 64; ++j) {
        int k = (i + j) & (N - 1);
        float4 qq = spos[k];
        float d2 = me.w + qq.w;
        d2 = fmaf(m2x, qq.x, d2);
        d2 = fmaf(m2y, qq.y, d2);
        d2 = fmaf(m2z, qq.z, d2);
        if (d2 < R2_GUARD) {                       // ~never taken
            float dx = me.x - qq.x, dy = me.y - qq.y, dz = me.z - qq.z;
            float e2 = dx * dx + dy * dy + dz * dz; // exact recompute
            if (e2 < R2) pen += MIN_DIST - sqrtf(e2);
        }
    }
    if (i < 64) {   // distance-64 pairs: count once
        int k = i + 64;
        float4 qq = spos[k];
        float d2 = me.w + qq.w;
        d2 = fmaf(m2x, qq.x, d2);
        d2 = fmaf(m2y, qq.y, d2);
        d2 = fmaf(m2z, qq.z, d2);
        if (d2 < R2_GUARD) {
            float dx = me.x - qq.x, dy = me.y - qq.y, dz = me.z - qq.z;
            float e2 = dx * dx + dy * dy + dz * dz;
            if (e2 < R2) pen += MIN_DIST - sqrtf(e2);
        }
    }

    // ---- energy work term: elementwise coalesced sum f * (p_next - p) ----
    float wrk = 0.f;
    if (t < T - 1) {
        const float* pf = frc + (size_t)f * (N * D);
        const float* p1 = pt + N * D;
        #pragma unroll
        for (int q = i; q < N * D; q += 128)
            wrk += pf[q] * (p1[q] - pt[q]);
    }

    // ---- stability (last 5 frames) and kinetic (first / last frame) ----
    float stab = 0.f, ke = 0.f;
    if (t >= T - 5) {
        const float* pv = vel + (size_t)f * (N * D);
        float vx = pv[3 * i], vy = pv[3 * i + 1], vz = pv[3 * i + 2];
        float v2 = vx * vx + vy * vy + vz * vz;
        stab = sqrtf(v2);
        if (t == T - 1) ke = 0.5f * v2;
    } else if (t == 0) {
        const float* pv = vel + (size_t)f * (N * D);
        #pragma unroll
        for (int q = i; q < N * D; q += 128) {
            float v = pv[q];
            ke += 0.5f * v * v;
        }
    }

    // ---- block reduction of (pen, wrk, stab, ke) ----
    float4 acc = make_float4(pen, wrk, stab, ke);
    #pragma unroll
    for (int off = 16; off > 0; off >>= 1) {
        acc.x += __shfl_down_sync(0xffffffffu, acc.x, off);
        acc.y += __shfl_down_sync(0xffffffffu, acc.y, off);
        acc.z += __shfl_down_sync(0xffffffffu, acc.z, off);
        acc.w += __shfl_down_sync(0xffffffffu, acc.w, off);
    }
    __shared__ float4 wsum[4];
    if ((i & 31) == 0) wsum[i >> 5] = acc;
    __syncthreads();
    if (i == 0) {
        float4 s = wsum[0];
        #pragma unroll
        for (int w = 1; w < 4; ++w) {
            s.x += wsum[w].x; s.y += wsum[w].y;
            s.z += wsum[w].z; s.w += wsum[w].w;
        }
        g_pen[f]  = s.x;
        g_work[f] = s.y;
        g_stab[f] = s.z;
        g_ke0[f]  = (t == 0)     ? s.w : 0.f;
        g_ke1[f]  = (t == T - 1) ? s.w : 0.f;
    }

    // ---- last-arriving block performs the deterministic final reduction ----
    __threadfence();
    __shared__ int is_last;
    if (i == 0) {
        unsigned int old = atomicAdd(&g_count, 1u);
        is_last = (old == FRAMES - 1) ? 1 : 0;
    }
    __syncthreads();
    if (!is_last) return;

    float pen_s = 0.f, wrk_s = 0.f, stab_s = 0.f, k0 = 0.f, k1 = 0.f;
    #pragma unroll 4
    for (int q = i; q < FRAMES; q += 128) {
        pen_s  += g_pen[q];
        wrk_s  += g_work[q];
        stab_s += g_stab[q];
        k0     += g_ke0[q];
        k1     += g_ke1[q];
    }
    #pragma unroll
    for (int off = 16; off > 0; off >>= 1) {
        pen_s  += __shfl_down_sync(0xffffffffu, pen_s,  off);
        wrk_s  += __shfl_down_sync(0xffffffffu, wrk_s,  off);
        stab_s += __shfl_down_sync(0xffffffffu, stab_s, off);
        k0     += __shfl_down_sync(0xffffffffu, k0,     off);
        k1     += __shfl_down_sync(0xffffffffu, k1,     off);
    }
    __shared__ float sm[4][5];
    if ((i & 31) == 0) {
        int w = i >> 5;
        sm[w][0] = pen_s; sm[w][1] = wrk_s; sm[w][2] = stab_s;
        sm[w][3] = k0;    sm[w][4] = k1;
    }
    __syncthreads();
    if (i == 0) {
        float sp = 0.f, sw = 0.f, ss = 0.f, s0 = 0.f, s1 = 0.f;
        #pragma unroll
        for (int wv = 0; wv < 4; ++wv) {
            sp += sm[wv][0]; sw += sm[wv][1]; ss += sm[wv][2];
            s0 += sm[wv][3]; s1 += sm[wv][4];
        }
        const float pen_loss  = sp / (float)B / ((float)T * (float)N * (float)(N - 1) * 0.5f);
        const float work_mean = sw / (float)(B * (T - 1) * N);
        const float stab_mean = ss / (float)(B * 5 * N);
        const float ks        = s0 / (float)(B * N);
        const float ke        = s1 / (float)(B * N);
        out[0] = 10.0f * pen_loss + stab_mean + 0.1f * fabsf(ke - ks - work_mean);
        g_count = 0u;   // self-reset for the next graph replay
    }
}

extern "C" void kernel_launch(void* const* d_in, const int* in_sizes, int n_in,
                              void* d_out, int out_size)
{
    const float* traj = (const float*)d_in[0];
    const float* vel  = (const float*)d_in[1];
    const float* frc  = (const float*)d_in[2];

    fused_kernel<<<FRAMES, 128>>>(traj, vel, frc, (float*)d_out);
}